// round 5
// baseline (speedup 1.0000x reference)
#include <cuda_runtime.h>
#include <cstdint>
#include <cstddef>

// ---- problem dims ----
#define BDIM 1024
#define VDIM 50000
#define DDIM 300
#define NPAD_OUT 320          // padded N for partials
#define MTILE 128
#define NTILE 160             // per-CTA N
#define KT 32                 // k per stage/chunk
#define NSPLIT 9
#define NCH 174               // chunks per split (9*174*32 = 50112 >= 50000, zero-filled tail)
#define STAGES 4

// SMEM layout (bytes), per stage: A tile 128 x 36 floats (rows padded 144B), B tile 32 x 168 floats
#define A_ROW_F 36
#define A_STAGE_BYTES (MTILE * A_ROW_F * 4)     // 18432
#define B_ROW_F 168
#define B_STAGE_BYTES (KT * B_ROW_F * 4)        // 21504
#define STAGE_BYTES (A_STAGE_BYTES + B_STAGE_BYTES)  // 39936
#define SMEM_TOTAL (STAGES * STAGE_BYTES)            // 159744

// split-K partials
__device__ float g_partial[NSPLIT * BDIM * NPAD_OUT];   // ~11.8 MB

// ---------------- helpers ----------------
__device__ __forceinline__ uint32_t smem_u32(const void* p) {
    uint32_t a;
    asm("{ .reg .u64 t; cvta.to.shared.u64 t, %1; cvt.u32.u64 %0, t; }" : "=r"(a) : "l"(p));
    return a;
}
__device__ __forceinline__ void cpa16(uint32_t dst, const void* src, int sz) {
    asm volatile("cp.async.cg.shared.global [%0], [%1], 16, %2;"
                 :: "r"(dst), "l"(src), "r"(sz) : "memory");
}
__device__ __forceinline__ void cp_commit() {
    asm volatile("cp.async.commit_group;" ::: "memory");
}
__device__ __forceinline__ void cp_wait3() {
    asm volatile("cp.async.wait_group %0;" :: "n"(STAGES - 1) : "memory");
}
__device__ __forceinline__ void ldmatrix_x4(uint32_t* r, uint32_t addr) {
    asm volatile("ldmatrix.sync.aligned.m8n8.x4.shared.b16 {%0,%1,%2,%3}, [%4];"
                 : "=r"(r[0]), "=r"(r[1]), "=r"(r[2]), "=r"(r[3]) : "r"(addr));
}
__device__ __forceinline__ void mma_tf32(float* c, const uint32_t* a, uint32_t b0, uint32_t b1) {
    asm volatile(
        "mma.sync.aligned.m16n8k8.row.col.f32.tf32.tf32.f32 "
        "{%0,%1,%2,%3}, {%4,%5,%6,%7}, {%8,%9}, {%0,%1,%2,%3};"
        : "+f"(c[0]), "+f"(c[1]), "+f"(c[2]), "+f"(c[3])
        : "r"(a[0]), "r"(a[1]), "r"(a[2]), "r"(a[3]), "r"(b0), "r"(b1));
}

// ---------------- GEMM: C_partial[ks] += A[m,:]W ----------------
__device__ __forceinline__ void load_stage(const float* __restrict__ A, const float* __restrict__ W,
                                           uint32_t sbase, int stage, int chunk,
                                           int mt, int nbase, int tid) {
    const int kbase = chunk * KT;
    const uint32_t abase = sbase + stage * STAGE_BYTES;
    const uint32_t bbase = abase + A_STAGE_BYTES;
    // A tile: 128 rows x 8 float4
#pragma unroll
    for (int t = 0; t < 4; t++) {
        int idx = tid + 256 * t;            // 0..1023
        int m = idx >> 3, q = idx & 7;
        int k = kbase + q * 4;
        const float* src = A + (size_t)(mt * MTILE + m) * VDIM + k;
        int sz = (k < VDIM) ? 16 : 0;
        cpa16(abase + m * (A_ROW_F * 4) + q * 16, sz ? src : A, sz);
    }
    // B tile: 32 rows x 40 float4
#pragma unroll
    for (int t = 0; t < 5; t++) {
        int idx = tid + 256 * t;            // 0..1279
        int r = idx / 40, q = idx - r * 40;
        int k = kbase + r;
        int n = nbase + q * 4;
        const float* src = W + (size_t)k * DDIM + n;
        int sz = (k < VDIM && (n + 4) <= DDIM) ? 16 : 0;
        cpa16(bbase + r * (B_ROW_F * 4) + q * 16, sz ? src : W, sz);
    }
    cp_commit();
}

__global__ void __launch_bounds__(256, 1)
gemm_kernel(const float* __restrict__ A, const float* __restrict__ W) {
    extern __shared__ char smem[];
    const uint32_t sbase = smem_u32(smem);
    const int tid = threadIdx.x;
    const int w = tid >> 5, lane = tid & 31;
    const int wm = w & 3, wn = w >> 2;          // warp grid 4(M) x 2(N)
    const int mt = blockIdx.x;                  // 0..7
    const int nt = blockIdx.y;                  // 0..1
    const int ks = blockIdx.z;                  // 0..8
    const int nbase = nt * NTILE;
    const int c0 = ks * NCH;

    const int lrow = lane >> 2, lcol = lane & 3;
    // ldmatrix per-thread row index: g = lane>>3 (matrix id), r = lane&7
    const int g = lane >> 3, rr = lane & 7;
    const int a_m_local = (g & 1) * 8 + rr;     // row within 16-row tile
    const int a_kgrp = g >> 1;                  // 0 or 1 (k0..3 / k4..7)

    float acc[2][10][4];
#pragma unroll
    for (int t = 0; t < 2; t++)
#pragma unroll
        for (int j = 0; j < 10; j++)
#pragma unroll
            for (int e = 0; e < 4; e++) acc[t][j][e] = 0.0f;

    // prologue: stages 0..2
#pragma unroll
    for (int s = 0; s < STAGES - 1; s++)
        load_stage(A, W, sbase, s, c0 + s, mt, nbase, tid);

    for (int i = 0; i < NCH; i++) {
        if (i + STAGES - 1 < NCH)
            load_stage(A, W, sbase, (i + STAGES - 1) & (STAGES - 1), c0 + i + STAGES - 1, mt, nbase, tid);
        else
            cp_commit();  // keep group accounting uniform
        cp_wait3();
        __syncthreads();

        const int stage = i & (STAGES - 1);
        const uint32_t a_smem = sbase + stage * STAGE_BYTES;
        const float* Bs = reinterpret_cast<const float*>(smem + stage * STAGE_BYTES + A_STAGE_BYTES);

#pragma unroll
        for (int kk = 0; kk < 4; kk++) {
            uint32_t afrag[2][4];
#pragma unroll
            for (int t = 0; t < 2; t++) {
                uint32_t addr = a_smem
                    + (uint32_t)(wm * 32 + t * 16 + a_m_local) * (A_ROW_F * 4)
                    + (uint32_t)(kk * 8 + a_kgrp * 4) * 4;
                ldmatrix_x4(afrag[t], addr);
            }
            const float* brow0 = Bs + (kk * 8 + lcol) * B_ROW_F + wn * 80 + lrow;
            const float* brow1 = brow0 + 4 * B_ROW_F;
#pragma unroll
            for (int j = 0; j < 10; j++) {
                uint32_t b0 = __float_as_uint(brow0[j * 8]);
                uint32_t b1 = __float_as_uint(brow1[j * 8]);
                mma_tf32(acc[0][j], afrag[0], b0, b1);
                mma_tf32(acc[1][j], afrag[1], b0, b1);
            }
        }
        __syncthreads();
    }

    // epilogue: write partials
#pragma unroll
    for (int t = 0; t < 2; t++) {
        int row0 = mt * MTILE + wm * 32 + t * 16 + lrow;
#pragma unroll
        for (int j = 0; j < 10; j++) {
            int col = nbase + wn * 80 + j * 8 + 2 * lcol;
            float* p0 = g_partial + ((size_t)ks * BDIM + row0) * NPAD_OUT + col;
            float* p1 = g_partial + ((size_t)ks * BDIM + row0 + 8) * NPAD_OUT + col;
            *reinterpret_cast<float2*>(p0) = make_float2(acc[t][j][0], acc[t][j][1]);
            *reinterpret_cast<float2*>(p1) = make_float2(acc[t][j][2], acc[t][j][3]);
        }
    }
}

// ---------------- reduce + L2 normalize ----------------
__global__ void __launch_bounds__(320) reduce_norm_kernel(float* __restrict__ out) {
    const int row = blockIdx.x;
    const int d = threadIdx.x;
    __shared__ float ssum[10];
    __shared__ float sinv;
    float a = 0.0f;
    if (d < DDIM) {
#pragma unroll
        for (int s = 0; s < NSPLIT; s++)
            a += g_partial[((size_t)s * BDIM + row) * NPAD_OUT + d];
    }
    float sq = a * a;
#pragma unroll
    for (int off = 16; off > 0; off >>= 1)
        sq += __shfl_xor_sync(0xFFFFFFFFu, sq, off);
    if ((threadIdx.x & 31) == 0) ssum[threadIdx.x >> 5] = sq;
    __syncthreads();
    if (threadIdx.x == 0) {
        float t = 0.0f;
#pragma unroll
        for (int i = 0; i < 10; i++) t += ssum[i];
        sinv = 1.0f / (sqrtf(t) + 1e-7f);
    }
    __syncthreads();
    if (d < DDIM)
        out[(size_t)row * DDIM + d] = a * sinv;
}

// ---------------- launch ----------------
extern "C" void kernel_launch(void* const* d_in, const int* in_sizes, int n_in,
                              void* d_out, int out_size) {
    const float* labels = (const float*)d_in[0];
    const float* weight = (const float*)d_in[1];
    if (n_in >= 2 && in_sizes[0] == VDIM * DDIM) {   // defensive: identify by size
        labels = (const float*)d_in[1];
        weight = (const float*)d_in[0];
    }
    float* out = (float*)d_out;

    // no static guard (harness rule); this call is capture-safe and idempotent
    cudaFuncSetAttribute(gemm_kernel, cudaFuncAttributeMaxDynamicSharedMemorySize, SMEM_TOTAL);

    gemm_kernel<<<dim3(BDIM / MTILE, 2, NSPLIT), 256, SMEM_TOTAL>>>(labels, weight);
    reduce_norm_kernel<<<BDIM, 320>>>(out);
}

// round 6
// speedup vs baseline: 1.3352x; 1.3352x over previous
#include <cuda_runtime.h>
#include <cuda_fp16.h>
#include <cstdint>
#include <cstddef>

// ---- problem dims ----
#define BDIM 1024
#define VDIM 50000
#define DDIM 300
#define NPAD_OUT 320
#define MTILE 128
#define NTILE 160
#define KT 32
#define NSPLIT 9
#define NCH 174               // 9*174*32 = 50112 >= 50000 (guarded tail)

// SMEM (fp16): A 128 rows x 32 halves, row padded to 80 B; B 32 rows x 160 halves, padded to 336 B
#define A_ROW_B 80
#define B_ROW_B 336
#define A_TILE_B (MTILE * A_ROW_B)        // 10240
#define B_TILE_B (KT * B_ROW_B)           // 10752
#define STAGE_B (A_TILE_B + B_TILE_B)     // 20992
// double buffered: 41984 B static shared (< 48 KB, no attribute needed)

__device__ float g_partial[NSPLIT * BDIM * NPAD_OUT];   // ~11.8 MB

// ---------------- helpers ----------------
__device__ __forceinline__ uint32_t smem_u32(const void* p) {
    uint32_t a;
    asm("{ .reg .u64 t; cvta.to.shared.u64 t, %1; cvt.u32.u64 %0, t; }" : "=r"(a) : "l"(p));
    return a;
}
__device__ __forceinline__ void ldmx4(uint32_t* r, uint32_t addr) {
    asm volatile("ldmatrix.sync.aligned.m8n8.x4.shared.b16 {%0,%1,%2,%3}, [%4];"
                 : "=r"(r[0]), "=r"(r[1]), "=r"(r[2]), "=r"(r[3]) : "r"(addr));
}
__device__ __forceinline__ void ldmx4t(uint32_t* r, uint32_t addr) {
    asm volatile("ldmatrix.sync.aligned.m8n8.x4.trans.shared.b16 {%0,%1,%2,%3}, [%4];"
                 : "=r"(r[0]), "=r"(r[1]), "=r"(r[2]), "=r"(r[3]) : "r"(addr));
}
__device__ __forceinline__ void mma16(float* c, const uint32_t* a, uint32_t b0, uint32_t b1) {
    asm volatile(
        "mma.sync.aligned.m16n8k16.row.col.f32.f16.f16.f32 "
        "{%0,%1,%2,%3}, {%4,%5,%6,%7}, {%8,%9}, {%0,%1,%2,%3};"
        : "+f"(c[0]), "+f"(c[1]), "+f"(c[2]), "+f"(c[3])
        : "r"(a[0]), "r"(a[1]), "r"(a[2]), "r"(a[3]), "r"(b0), "r"(b1));
}
__device__ __forceinline__ uint32_t h2u(__half2 h) {
    union { __half2 h; uint32_t u; } c; c.h = h; return c.u;
}

// ---------------- GEMM (fp16 MMA, fused fp32->fp16 convert) ----------------
__global__ void __launch_bounds__(256, 1)
gemm_kernel(const float* __restrict__ A, const float* __restrict__ W) {
    __shared__ __align__(128) unsigned char smem[2 * STAGE_B];
    const uint32_t sbase = smem_u32(smem);
    const int tid = threadIdx.x, w = tid >> 5, lane = tid & 31;
    const int wm = w & 3, wn = w >> 2;            // warp grid 4(M) x 2(N)
    const int mt = blockIdx.x;                    // 0..7
    const int nt = blockIdx.y;                    // 0..1
    const int ks = blockIdx.z;                    // 0..8
    const int nbase = nt * NTILE;
    const int c0 = ks * NCH;

    // ---- LDG assignments (fixed per thread) ----
    const int arow = tid >> 3, aq = tid & 7;      // A: rows arow+32i, float4 #aq
    const float* aptr[4];
#pragma unroll
    for (int i = 0; i < 4; i++)
        aptr[i] = A + (size_t)(mt * MTILE + arow + 32 * i) * VDIM + aq * 4;

    int bro[5]; const float* bptr[5]; bool bok[5]; uint32_t b_sts[5];
#pragma unroll
    for (int i = 0; i < 5; i++) {
        int idx = tid + 256 * i;
        int r = idx / 40, q = idx - 40 * r;       // B: k-row r, float4 #q
        bro[i] = r;
        bok[i] = (nbase + q * 4) < DDIM;          // 300 % 4 == 0: full or none
        bptr[i] = W + (size_t)r * DDIM + nbase + q * 4;
        b_sts[i] = (uint32_t)(A_TILE_B + r * B_ROW_B + q * 8);
    }
    const uint32_t a_sts = (uint32_t)(arow * A_ROW_B + aq * 8);

    // ---- ldmatrix per-lane base offsets ----
    const int al = lane & 15, ak = lane >> 4;
    const uint32_t a_lm = (uint32_t)((wm * 32 + al) * A_ROW_B + ak * 16);
    const int bl = lane & 7, bk8 = (lane >> 3) & 1, bn8 = lane >> 4;
    const uint32_t b_lm = (uint32_t)(A_TILE_B + (bk8 * 8 + bl) * B_ROW_B
                                     + (wn * 80 + bn8 * 8) * 2);

    float4 sa[4], sb[5];      // staging registers (one chunk ahead)

    float acc[2][10][4];
#pragma unroll
    for (int t = 0; t < 2; t++)
#pragma unroll
        for (int j = 0; j < 10; j++)
#pragma unroll
            for (int e = 0; e < 4; e++) acc[t][j][e] = 0.0f;

    // ---- ldg / sts helpers ----
    auto ldg_chunk = [&](int chunk) {
        const int kb = chunk * KT;
        const bool aok = (kb + aq * 4 + 4) <= VDIM;   // VDIM % 4 == 0
#pragma unroll
        for (int i = 0; i < 4; i++)
            sa[i] = aok ? *reinterpret_cast<const float4*>(aptr[i] + kb)
                        : make_float4(0.f, 0.f, 0.f, 0.f);
#pragma unroll
        for (int i = 0; i < 5; i++) {
            bool ok = bok[i] && (kb + bro[i]) < VDIM;
            sb[i] = ok ? *reinterpret_cast<const float4*>(bptr[i] + (size_t)kb * DDIM)
                       : make_float4(0.f, 0.f, 0.f, 0.f);
        }
    };
    auto sts_chunk = [&](uint32_t bufoff) {
        unsigned char* base = smem + bufoff;
#pragma unroll
        for (int i = 0; i < 4; i++) {
            uint32_t u0 = h2u(__floats2half2_rn(sa[i].x, sa[i].y));
            uint32_t u1 = h2u(__floats2half2_rn(sa[i].z, sa[i].w));
            *reinterpret_cast<uint2*>(base + a_sts + i * 32 * A_ROW_B) = make_uint2(u0, u1);
        }
#pragma unroll
        for (int i = 0; i < 5; i++) {
            uint32_t u0 = h2u(__floats2half2_rn(sb[i].x, sb[i].y));
            uint32_t u1 = h2u(__floats2half2_rn(sb[i].z, sb[i].w));
            *reinterpret_cast<uint2*>(base + b_sts[i]) = make_uint2(u0, u1);
        }
    };

    // ---- pipeline ----
    ldg_chunk(c0);
    sts_chunk(0);
    __syncthreads();

    for (int i = 0; i < NCH; i++) {
        if (i + 1 < NCH) ldg_chunk(c0 + i + 1);   // latency hidden by MMAs below

        const uint32_t buf = (uint32_t)((i & 1) * STAGE_B);
        const uint32_t aa = sbase + buf + a_lm;
        const uint32_t bb = sbase + buf + b_lm;
#pragma unroll
        for (int kstep = 0; kstep < 2; kstep++) {
            uint32_t af0[4], af1[4];
            ldmx4(af0, aa + kstep * 32);                      // M tile 0 (rows wm*32..+15)
            ldmx4(af1, aa + 16 * A_ROW_B + kstep * 32);       // M tile 1 (+16 rows)
#pragma unroll
            for (int jp = 0; jp < 5; jp++) {
                uint32_t bf[4];
                ldmx4t(bf, bb + kstep * 16 * B_ROW_B + jp * 32);   // 2 n8 tiles
                mma16(acc[0][2 * jp],     af0, bf[0], bf[1]);
                mma16(acc[1][2 * jp],     af1, bf[0], bf[1]);
                mma16(acc[0][2 * jp + 1], af0, bf[2], bf[3]);
                mma16(acc[1][2 * jp + 1], af1, bf[2], bf[3]);
            }
        }
        __syncthreads();                                  // done reading buf i
        if (i + 1 < NCH) {
            sts_chunk((uint32_t)(((i + 1) & 1) * STAGE_B));
            __syncthreads();                              // buf i+1 visible
        }
    }

    // ---- epilogue: write split-K partials ----
    const int lrow = lane >> 2, lcol = lane & 3;
#pragma unroll
    for (int t = 0; t < 2; t++) {
        int row0 = mt * MTILE + wm * 32 + t * 16 + lrow;
#pragma unroll
        for (int j = 0; j < 10; j++) {
            int col = nbase + wn * 80 + j * 8 + 2 * lcol;
            float* p0 = g_partial + ((size_t)ks * BDIM + row0) * NPAD_OUT + col;
            float* p1 = g_partial + ((size_t)ks * BDIM + row0 + 8) * NPAD_OUT + col;
            *reinterpret_cast<float2*>(p0) = make_float2(acc[t][j][0], acc[t][j][1]);
            *reinterpret_cast<float2*>(p1) = make_float2(acc[t][j][2], acc[t][j][3]);
        }
    }
}

// ---------------- reduce + L2 normalize ----------------
__global__ void __launch_bounds__(320) reduce_norm_kernel(float* __restrict__ out) {
    const int row = blockIdx.x;
    const int d = threadIdx.x;
    __shared__ float ssum[10];
    __shared__ float sinv;
    float a = 0.0f;
    if (d < DDIM) {
#pragma unroll
        for (int s = 0; s < NSPLIT; s++)
            a += g_partial[((size_t)s * BDIM + row) * NPAD_OUT + d];
    }
    float sq = a * a;
#pragma unroll
    for (int off = 16; off > 0; off >>= 1)
        sq += __shfl_xor_sync(0xFFFFFFFFu, sq, off);
    if ((threadIdx.x & 31) == 0) ssum[threadIdx.x >> 5] = sq;
    __syncthreads();
    if (threadIdx.x == 0) {
        float t = 0.0f;
#pragma unroll
        for (int i = 0; i < 10; i++) t += ssum[i];
        sinv = 1.0f / (sqrtf(t) + 1e-7f);
    }
    __syncthreads();
    if (d < DDIM)
        out[(size_t)row * DDIM + d] = a * sinv;
}

// ---------------- launch ----------------
extern "C" void kernel_launch(void* const* d_in, const int* in_sizes, int n_in,
                              void* d_out, int out_size) {
    const float* labels = (const float*)d_in[0];
    const float* weight = (const float*)d_in[1];
    if (n_in >= 2 && in_sizes[0] == VDIM * DDIM) {   // defensive: identify by size
        labels = (const float*)d_in[1];
        weight = (const float*)d_in[0];
    }
    float* out = (float*)d_out;

    gemm_kernel<<<dim3(BDIM / MTILE, 2, NSPLIT), 256>>>(labels, weight);
    reduce_norm_kernel<<<BDIM, 320>>>(out);
}